// round 14
// baseline (speedup 1.0000x reference)
#include <cuda_runtime.h>
#include <cstdint>

#define N_NODES 10000
#define N_EDGES 100000
#define F 64
#define NTYPES 10
#define WT_ELEMS (NTYPES * F * F)        // 40960 floats = 160KB
#define GRP 8                             // edges per warp group (same type)
#define SEG_CAP 12288                     // per-type segment capacity
#define EDGE_THREADS 768
#define EDGE_WARPS (EDGE_THREADS / 32)    // 24
#define NBLOCKS 148                       // one CTA per SM (co-resident)
#define SH_H_FLOATS (EDGE_WARPS * GRP * F)        // 12288 floats = 48KB
#define SMEM_BYTES ((WT_ELEMS + SH_H_FLOATS) * 4)  // 208KB

// ---- device scratch (no allocs allowed) ----
__device__ float g_deg_out[N_NODES];
__device__ float g_deg_in[N_NODES];
__device__ int   g_esrc[NTYPES * SEG_CAP];     // type-segmented src
__device__ int   g_edst[NTYPES * SEG_CAP];     // type-segmented dst
__device__ int   g_cursor[NTYPES];             // per-type counts
__device__ unsigned g_cnt = 0;                 // barrier arrival counter
__device__ unsigned g_gen = 0;                 // barrier generation

// Device-wide barrier. Safe: grid == 148 CTAs, all resident (208KB smem
// forces 1 CTA/SM on 148 SMs). g_cnt returns to 0 every barrier; g_gen
// increases monotonically (compared relatively), so graph replays are fine.
__device__ __forceinline__ void grid_barrier() {
    __syncthreads();
    if (threadIdx.x == 0) {
        __threadfence();
        unsigned gen = *(volatile unsigned*)&g_gen;
        if (atomicAdd(&g_cnt, 1) == NBLOCKS - 1) {
            g_cnt = 0;
            __threadfence();
            atomicExch(&g_gen, gen + 1);
        } else {
            while (*(volatile unsigned*)&g_gen == gen) { }
        }
        __threadfence();
    }
    __syncthreads();
}

// ------------------------------------------------------------------
// Single persistent kernel: Phase A (init + W smem staging) -> barrier ->
// Phase B (degrees + type-segmented edge scatter) -> barrier ->
// Phase C (edge matvec + fused norm + atomic aggregate).
__global__ __launch_bounds__(EDGE_THREADS, 1) void rconv_mega(
    const float2* __restrict__ feat2,
    const int*    __restrict__ src,
    const int*    __restrict__ dst,
    const int*    __restrict__ order,
    const float*  __restrict__ emb,
    const float4* __restrict__ bias4,
    float*        __restrict__ acc)
{
    extern __shared__ float smem[];
    float* wt  = smem;                 // [NTYPES][32][128] floats (interleaved)
    float* shh = smem + WT_ELEMS;      // phase A: padded temp; phase C: h tiles

    const int gtid    = blockIdx.x * blockDim.x + threadIdx.x;
    const int gstride = gridDim.x * blockDim.x;
    const int lane    = threadIdx.x & 31;

    // ================= Phase A =================
    // acc := bias (folds the final bias add), zero degrees & cursors.
    {
        float4* acc4 = (float4*)acc;
        for (int i = gtid; i < N_NODES * (F / 4); i += gstride)
            acc4[i] = bias4[i & 15];
        for (int j = gtid; j < N_NODES; j += gstride) {
            g_deg_out[j] = 0.f;
            g_deg_in[j]  = 0.f;
        }
        if (gtid < NTYPES) g_cursor[gtid] = 0;
    }
    // Build interleaved W in THIS block's smem, one type at a time:
    //   raw emb (coalesced LDG) -> padded smem temp (stride 66, no STS
    //   conflicts) -> interleaved wt (4-way LDS conflicts, conflict-free STS).
    // Interleaved: float4 wt4[r][j*32+L] = {W[2L][2j], W[2L][2j+1],
    //                                       W[2L+1][2j], W[2L+1][2j+1]}.
    {
        float4* wt4 = (float4*)wt;
        for (int r = 0; r < NTYPES; r++) {
            for (int idx = threadIdx.x; idx < F * F; idx += blockDim.x) {
                int o = idx >> 6, i = idx & 63;
                shh[o * 66 + i] = emb[(r << 12) + idx];
            }
            __syncthreads();
            for (int d = threadIdx.x; d < 1024; d += blockDim.x) {
                int j = d >> 5, L = d & 31;
                float2 t0 = *(const float2*)&shh[(2 * L)     * 66 + 2 * j];
                float2 t1 = *(const float2*)&shh[(2 * L + 1) * 66 + 2 * j];
                wt4[(r << 10) + d] = make_float4(t0.x, t0.y, t1.x, t1.y);
            }
            __syncthreads();
        }
    }
    grid_barrier();

    // ================= Phase B =================
    // Degrees + single-pass type-segmented scatter (one edge per thread;
    // 148*768 = 113664 >= N_EDGES). Warp-aggregated cursor atomics.
    {
        int e = gtid;
        bool v = e < N_EDGES;
        unsigned act = __ballot_sync(0xffffffffu, v);
        if (v) {
            int s = src[e], d = dst[e], t = order[e];
            atomicAdd(&g_deg_out[s], 1.0f);
            atomicAdd(&g_deg_in[d], 1.0f);
            unsigned m = __match_any_sync(act, t);
            int leader = __ffs(m) - 1;
            int rank = __popc(m & ((1u << lane) - 1));
            int base = 0;
            if (lane == leader) base = atomicAdd(&g_cursor[t], __popc(m));
            base = __shfl_sync(m, base, leader);
            int pos = t * SEG_CAP + base + rank;
            g_esrc[pos] = s;
            g_edst[pos] = d;
        }
    }
    grid_barrier();

    // ================= Phase C =================
    __shared__ int s_lim[NTYPES];        // segment end index (base + count)
    __shared__ int s_goff[NTYPES + 1];   // group prefix
    if (threadIdx.x == 0) {
        int g = 0;
        for (int t = 0; t < NTYPES; t++) {
            int h = g_cursor[t];
            s_lim[t] = t * SEG_CAP + h;
            s_goff[t] = g;
            g += (h + GRP - 1) / GRP;
        }
        s_goff[NTYPES] = g;
    }
    __syncthreads();

    const int wl     = threadIdx.x >> 5;
    const int warp   = gtid >> 5;
    const int nwarps = gstride >> 5;
    const int n_groups = s_goff[NTYPES];
    float2* myh = (float2*)(shh + wl * (GRP * F));   // [GRP][32] float2

    for (int gi = warp; gi < n_groups; gi += nwarps) {
        int t = 0;
        while (gi >= s_goff[t + 1]) t++;
        const int base = t * SEG_CAP + (gi - s_goff[t]) * GRP;
        const int lim  = s_lim[t];

        __syncwarp();   // previous iteration's readers done before overwrite
        int dd[GRP];
        #pragma unroll
        for (int k = 0; k < GRP; k++) {
            int idx = min(base + k, lim - 1);
            int s = __ldg(&g_esrc[idx]);
            dd[k] = __ldg(&g_edst[idx]);
            float sc = rsqrtf(fmaxf(__ldg(&g_deg_out[s]), 1.0f));  // broadcast
            float2 v = feat2[s * 32 + lane];
            myh[k * 32 + lane] = make_float2(v.x * sc, v.y * sc);
        }
        __syncwarp();

        const ulonglong2* __restrict__ wv = (const ulonglong2*)(wt + (t << 12));
        const ulonglong2* __restrict__ hp = (const ulonglong2*)myh;  // [GRP][16]
        uint64_t a0[GRP], a1[GRP];
        #pragma unroll
        for (int k = 0; k < GRP; k++) { a0[k] = 0ull; a1[k] = 0ull; }

        #pragma unroll
        for (int j2 = 0; j2 < 16; j2++) {
            const ulonglong2 w0 = wv[(2 * j2) * 32 + lane];       // j = 2*j2
            const ulonglong2 w1 = wv[(2 * j2 + 1) * 32 + lane];   // j = 2*j2+1
            #pragma unroll
            for (int k = 0; k < GRP; k++) {
                const ulonglong2 h = hp[k * 16 + j2];   // h[4j2..4j2+3] bcast
                asm("fma.rn.f32x2 %0, %1, %2, %0;" : "+l"(a0[k]) : "l"(w0.x), "l"(h.x));
                asm("fma.rn.f32x2 %0, %1, %2, %0;" : "+l"(a1[k]) : "l"(w0.y), "l"(h.x));
                asm("fma.rn.f32x2 %0, %1, %2, %0;" : "+l"(a0[k]) : "l"(w1.x), "l"(h.y));
                asm("fma.rn.f32x2 %0, %1, %2, %0;" : "+l"(a1[k]) : "l"(w1.y), "l"(h.y));
            }
        }

        #pragma unroll
        for (int k = 0; k < GRP; k++) {
            float sin_ = rsqrtf(fmaxf(__ldg(&g_deg_in[dd[k]]), 1.0f));
            float p, q, r2, s2;
            asm("mov.b64 {%0, %1}, %2;" : "=f"(p),  "=f"(q)  : "l"(a0[k]));
            asm("mov.b64 {%0, %1}, %2;" : "=f"(r2), "=f"(s2) : "l"(a1[k]));
            float ax = (p + q) * sin_;     // output 2L
            float ay = (r2 + s2) * sin_;   // output 2L+1
            float bx = __shfl_down_sync(0xffffffffu, ax, 1);
            float by = __shfl_down_sync(0xffffffffu, ay, 1);
            if ((base + k) < lim && !(lane & 1)) {
                float* ptr = &acc[dd[k] * F + 2 * lane];
                asm volatile("red.global.add.v4.f32 [%0], {%1, %2, %3, %4};"
                             :: "l"(ptr), "f"(ax), "f"(ay), "f"(bx), "f"(by)
                             : "memory");
            }
        }
    }
}

extern "C" void kernel_launch(void* const* d_in, const int* in_sizes, int n_in,
                              void* d_out, int out_size) {
    const float* feat = (const float*)d_in[0];
    const int*   src  = (const int*)  d_in[1];
    const int*   dst  = (const int*)  d_in[2];
    const int*   ordr = (const int*)  d_in[3];
    const float* emb  = (const float*)d_in[4];
    const float* bias = (const float*)d_in[5];
    float* out = (float*)d_out;

    static bool attr_set = false;
    if (!attr_set) {
        cudaFuncSetAttribute(rconv_mega,
                             cudaFuncAttributeMaxDynamicSharedMemorySize,
                             SMEM_BYTES);
        attr_set = true;
    }

    rconv_mega<<<NBLOCKS, EDGE_THREADS, SMEM_BYTES>>>(
        (const float2*)feat, src, dst, ordr, emb, (const float4*)bias, out);
}

// round 15
// speedup vs baseline: 1.1498x; 1.1498x over previous
#include <cuda_runtime.h>
#include <cstdint>

#define N_NODES 10000
#define N_EDGES 100000
#define F 64
#define NTYPES 10
#define WT_ELEMS (NTYPES * F * F)        // 40960 floats = 160KB
#define GRP 8                             // edges per warp group (same type)
#define SEG_CAP 12288                     // per-type segment capacity
#define TPH 5                             // types per half (CTA parity)
#define EDGE_THREADS 512
#define EDGE_WARPS (EDGE_THREADS / 32)    // 16
#define NPAIRS 148
#define W_HALF_FLOATS (TPH * F * F)               // 20480 floats = 80KB
#define SH_H_FLOATS (EDGE_WARPS * GRP * F)        // 8192 floats = 32KB
#define SMEM_EDGE_BYTES ((W_HALF_FLOATS + SH_H_FLOATS) * 4)  // 114688B = 112KB

// ---- device scratch (no allocs allowed) ----
__device__ float g_deg_out[N_NODES];
__device__ float g_deg_in[N_NODES];
__device__ float g_wt[WT_ELEMS];               // pre-interleaved weights
__device__ int   g_esrc[NTYPES * SEG_CAP];     // type-segmented src
__device__ int   g_edst[NTYPES * SEG_CAP];     // type-segmented dst
__device__ int   g_cursor[NTYPES];             // per-type counts

// ------------------------------------------------------------------
// Kernel 1: W interleave via padded-smem transpose (both GMEM sides
// coalesced), plus zero degrees/cursors.
// Interleaved: float4 wt4[r][j*32+L] = { W[2L][2j], W[2L][2j+1],
//                                        W[2L+1][2j], W[2L+1][2j+1] }.
__global__ void rconv_prep(const float* __restrict__ emb) {
    __shared__ float sh[F * 66];
    int gtid = blockIdx.x * blockDim.x + threadIdx.x;
    for (int j = gtid; j < N_NODES; j += gridDim.x * blockDim.x) {
        g_deg_out[j] = 0.f;
        g_deg_in[j]  = 0.f;
    }
    if (gtid < NTYPES) g_cursor[gtid] = 0;

    if (blockIdx.x < NTYPES) {
        int r = blockIdx.x;
        for (int idx = threadIdx.x; idx < F * F; idx += blockDim.x) {
            int o = idx >> 6, i = idx & 63;
            sh[o * 66 + i] = emb[(r << 12) + idx];
        }
        __syncthreads();
        float4* wt4 = (float4*)g_wt;
        for (int d = threadIdx.x; d < 1024; d += blockDim.x) {
            int j = d >> 5, L = d & 31;
            float2 t0 = *(const float2*)&sh[(2 * L)     * 66 + 2 * j];
            float2 t1 = *(const float2*)&sh[(2 * L + 1) * 66 + 2 * j];
            wt4[(r << 10) + d] = make_float4(t0.x, t0.y, t1.x, t1.y);
        }
    }
}

// ------------------------------------------------------------------
// Kernel 2: acc := bias (folds final bias add) fused with degrees +
// single-pass type-segmented scatter (warp-aggregated cursor atomics).
__global__ void rconv_init_scatter(float4* __restrict__ acc4,
                                   const float4* __restrict__ bias4,
                                   const int* __restrict__ src,
                                   const int* __restrict__ dst,
                                   const int* __restrict__ order) {
    const int tid  = blockIdx.x * blockDim.x + threadIdx.x;
    const int lane = threadIdx.x & 31;
    if (tid < N_NODES * (F / 4))
        acc4[tid] = bias4[tid & 15];

    int e = tid;
    bool v = e < N_EDGES;
    unsigned act = __ballot_sync(0xffffffffu, v);
    if (v) {
        int s = src[e], d = dst[e], t = order[e];
        atomicAdd(&g_deg_out[s], 1.0f);
        atomicAdd(&g_deg_in[d], 1.0f);
        unsigned m = __match_any_sync(act, t);
        int leader = __ffs(m) - 1;
        int rank = __popc(m & ((1u << lane) - 1));
        int base = 0;
        if (lane == leader) base = atomicAdd(&g_cursor[t], __popc(m));
        base = __shfl_sync(m, base, leader);
        int pos = t * SEG_CAP + base + rank;
        g_esrc[pos] = s;
        g_edst[pos] = d;
    }
}

// ------------------------------------------------------------------
// Kernel 3: edge matvec. W split across CTA parity: even CTAs hold types
// 0..4, odd CTAs types 5..9 -> 112KB smem/CTA -> TWO co-resident CTAs/SM
// (32 warps/SM, vs 24 before) to cover the LDS/gather latency that ncu
// showed as the bottleneck (issue=25.8% at occ=37.6%).
// Inner loop: packed fma.rn.f32x2, operands straight from LDS.128; epilogue
// scales by in_deg^{-1/2}(dst) and emits red.global.add.v4.f32.
__global__ __launch_bounds__(EDGE_THREADS, 2) void rconv_edges(
    const float2* __restrict__ feat2, float* __restrict__ acc)
{
    extern __shared__ float smem[];
    float* wt  = smem;                     // [TPH][32][128] interleaved
    float* shh = smem + W_HALF_FLOATS;     // [EDGE_WARPS][GRP][64]

    const int half  = blockIdx.x & 1;
    const int tbase = half * TPH;

    {   // coalesced float4 copy of this half's pre-interleaved weights
        const float4* __restrict__ w4 = (const float4*)g_wt + (tbase << 10);
        float4* wt4 = (float4*)wt;
        for (int i = threadIdx.x; i < W_HALF_FLOATS / 4; i += blockDim.x)
            wt4[i] = w4[i];
    }
    __shared__ int s_lim[TPH];
    __shared__ int s_goff[TPH + 1];
    if (threadIdx.x == 0) {
        int g = 0;
        for (int t = 0; t < TPH; t++) {
            int h = g_cursor[tbase + t];
            s_lim[t] = (tbase + t) * SEG_CAP + h;
            s_goff[t] = g;
            g += (h + GRP - 1) / GRP;
        }
        s_goff[TPH] = g;
    }
    __syncthreads();

    const int lane   = threadIdx.x & 31;
    const int wl     = threadIdx.x >> 5;
    const int warp   = (blockIdx.x >> 1) * EDGE_WARPS + wl;   // id within half
    const int nwarps = (gridDim.x >> 1) * EDGE_WARPS;
    const int n_groups = s_goff[TPH];
    float2* myh = (float2*)(shh + wl * (GRP * F));   // [GRP][32] float2

    for (int gi = warp; gi < n_groups; gi += nwarps) {
        int tl = 0;
        while (gi >= s_goff[tl + 1]) tl++;
        const int base = (tbase + tl) * SEG_CAP + (gi - s_goff[tl]) * GRP;
        const int lim  = s_lim[tl];

        __syncwarp();   // previous iteration's readers done before overwrite
        int dd[GRP];
        #pragma unroll
        for (int k = 0; k < GRP; k++) {
            int idx = min(base + k, lim - 1);
            int s = __ldg(&g_esrc[idx]);
            dd[k] = __ldg(&g_edst[idx]);
            float sc = rsqrtf(fmaxf(__ldg(&g_deg_out[s]), 1.0f));  // broadcast
            float2 v = feat2[s * 32 + lane];
            myh[k * 32 + lane] = make_float2(v.x * sc, v.y * sc);
        }
        __syncwarp();

        const ulonglong2* __restrict__ wv = (const ulonglong2*)(wt + (tl << 12));
        const ulonglong2* __restrict__ hp = (const ulonglong2*)myh;  // [GRP][16]
        uint64_t a0[GRP], a1[GRP];
        #pragma unroll
        for (int k = 0; k < GRP; k++) { a0[k] = 0ull; a1[k] = 0ull; }

        #pragma unroll
        for (int j2 = 0; j2 < 16; j2++) {
            const ulonglong2 w0 = wv[(2 * j2) * 32 + lane];       // j = 2*j2
            const ulonglong2 w1 = wv[(2 * j2 + 1) * 32 + lane];   // j = 2*j2+1
            #pragma unroll
            for (int k = 0; k < GRP; k++) {
                const ulonglong2 h = hp[k * 16 + j2];   // h[4j2..4j2+3] bcast
                asm("fma.rn.f32x2 %0, %1, %2, %0;" : "+l"(a0[k]) : "l"(w0.x), "l"(h.x));
                asm("fma.rn.f32x2 %0, %1, %2, %0;" : "+l"(a1[k]) : "l"(w0.y), "l"(h.x));
                asm("fma.rn.f32x2 %0, %1, %2, %0;" : "+l"(a0[k]) : "l"(w1.x), "l"(h.y));
                asm("fma.rn.f32x2 %0, %1, %2, %0;" : "+l"(a1[k]) : "l"(w1.y), "l"(h.y));
            }
        }

        #pragma unroll
        for (int k = 0; k < GRP; k++) {
            float sin_ = rsqrtf(fmaxf(__ldg(&g_deg_in[dd[k]]), 1.0f));
            float p, q, r2, s2;
            asm("mov.b64 {%0, %1}, %2;" : "=f"(p),  "=f"(q)  : "l"(a0[k]));
            asm("mov.b64 {%0, %1}, %2;" : "=f"(r2), "=f"(s2) : "l"(a1[k]));
            float ax = (p + q) * sin_;     // output 2L
            float ay = (r2 + s2) * sin_;   // output 2L+1
            float bx = __shfl_down_sync(0xffffffffu, ax, 1);
            float by = __shfl_down_sync(0xffffffffu, ay, 1);
            if ((base + k) < lim && !(lane & 1)) {
                float* ptr = &acc[dd[k] * F + 2 * lane];
                asm volatile("red.global.add.v4.f32 [%0], {%1, %2, %3, %4};"
                             :: "l"(ptr), "f"(ax), "f"(ay), "f"(bx), "f"(by)
                             : "memory");
            }
        }
    }
}

extern "C" void kernel_launch(void* const* d_in, const int* in_sizes, int n_in,
                              void* d_out, int out_size) {
    const float* feat = (const float*)d_in[0];
    const int*   src  = (const int*)  d_in[1];
    const int*   dst  = (const int*)  d_in[2];
    const int*   ordr = (const int*)  d_in[3];
    const float* emb  = (const float*)d_in[4];
    const float* bias = (const float*)d_in[5];
    float* out = (float*)d_out;

    static bool attr_set = false;
    if (!attr_set) {
        cudaFuncSetAttribute(rconv_edges,
                             cudaFuncAttributeMaxDynamicSharedMemorySize,
                             SMEM_EDGE_BYTES);
        attr_set = true;
    }

    rconv_prep<<<64, 256>>>(emb);
    rconv_init_scatter<<<(N_NODES * (F / 4) + 255) / 256, 256>>>(
        (float4*)out, (const float4*)bias, src, dst, ordr);
    rconv_edges<<<2 * NPAIRS, EDGE_THREADS, SMEM_EDGE_BYTES>>>(
        (const float2*)feat, out);
}

// round 17
// speedup vs baseline: 1.6836x; 1.4642x over previous
#include <cuda_runtime.h>
#include <cuda_bf16.h>
#include <cstdint>

#define N_NODES 10000
#define N_EDGES 100000
#define F 64
#define NTYPES 10
#define WT_ELEMS (NTYPES * F * F)      // 40960
#define SEG_CAP 12288
#define TILE_M 128
#define SMEM_BYTES (49152 + 1024)      // A_hi/A_lo 16K + B_hi/B_lo 8K + align

// ---- device scratch (no allocs allowed) ----
__device__ float g_deg_out[N_NODES];
__device__ float g_deg_in[N_NODES];
__device__ __nv_bfloat16 g_whi[WT_ELEMS];   // W split hi (bf16), [t][o][i]
__device__ __nv_bfloat16 g_wlo[WT_ELEMS];   // W split lo
__device__ int g_esrc[NTYPES * SEG_CAP];
__device__ int g_edst[NTYPES * SEG_CAP];
__device__ int g_cursor[NTYPES];

#define SWZ(x) ((x) ^ (((x) >> 3) & 0x70))

static __device__ __forceinline__ uint32_t smem_u32(const void* p) {
    uint32_t a;
    asm("{ .reg .u64 t; cvta.to.shared.u64 t, %1; cvt.u32.u64 %0, t; }" : "=r"(a) : "l"(p));
    return a;
}
static __device__ __forceinline__ void ldsm_x4(uint32_t& r0, uint32_t& r1,
                                               uint32_t& r2, uint32_t& r3, uint32_t a) {
    asm volatile("ldmatrix.sync.aligned.m8n8.x4.shared.b16 {%0,%1,%2,%3}, [%4];"
                 : "=r"(r0), "=r"(r1), "=r"(r2), "=r"(r3) : "r"(a));
}
static __device__ __forceinline__ void mma_bf16(float* c, const uint32_t* a, const uint32_t* b) {
    asm volatile("mma.sync.aligned.m16n8k16.row.col.f32.bf16.bf16.f32 "
                 "{%0,%1,%2,%3}, {%4,%5,%6,%7}, {%8,%9}, {%0,%1,%2,%3};"
                 : "+f"(c[0]), "+f"(c[1]), "+f"(c[2]), "+f"(c[3])
                 : "r"(a[0]), "r"(a[1]), "r"(a[2]), "r"(a[3]), "r"(b[0]), "r"(b[1]));
}
static __device__ __forceinline__ void red2(float* p, float a, float b) {
    asm volatile("red.global.add.v2.f32 [%0], {%1, %2};" :: "l"(p), "f"(a), "f"(b) : "memory");
}

// ------------------------------------------------------------------
// Kernel 1: zero degrees/cursors + Dekker-split W into bf16 hi/lo tables.
__global__ void rconv_prep(const float* __restrict__ emb) {
    int tid = blockIdx.x * blockDim.x + threadIdx.x;
    int stride = gridDim.x * blockDim.x;
    for (int j = tid; j < N_NODES; j += stride) { g_deg_out[j] = 0.f; g_deg_in[j] = 0.f; }
    if (tid < NTYPES) g_cursor[tid] = 0;
    for (int i = tid; i < WT_ELEMS; i += stride) {
        float x = emb[i];
        __nv_bfloat16 h = __float2bfloat16_rn(x);
        float r = x - __bfloat162float(h);
        g_whi[i] = h;
        g_wlo[i] = __float2bfloat16_rn(r);
    }
}

// ------------------------------------------------------------------
// Kernel 2: acc := bias + degrees + single-pass type-segmented scatter.
__global__ void rconv_init_scatter(float4* __restrict__ acc4,
                                   const float4* __restrict__ bias4,
                                   const int* __restrict__ src,
                                   const int* __restrict__ dst,
                                   const int* __restrict__ order) {
    const int tid  = blockIdx.x * blockDim.x + threadIdx.x;
    const int lane = threadIdx.x & 31;
    if (tid < N_NODES * (F / 4))
        acc4[tid] = bias4[tid & 15];

    int e = tid;
    bool v = e < N_EDGES;
    unsigned act = __ballot_sync(0xffffffffu, v);
    if (v) {
        int s = src[e], d = dst[e], t = order[e];
        atomicAdd(&g_deg_out[s], 1.0f);
        atomicAdd(&g_deg_in[d], 1.0f);
        unsigned m = __match_any_sync(act, t);
        int leader = __ffs(m) - 1;
        int rank = __popc(m & ((1u << lane) - 1));
        int base = 0;
        if (lane == leader) base = atomicAdd(&g_cursor[t], __popc(m));
        base = __shfl_sync(m, base, leader);
        int pos = t * SEG_CAP + base + rank;
        g_esrc[pos] = s;
        g_edst[pos] = d;
    }
}

// ------------------------------------------------------------------
// Kernel 3: HMMA edge kernel. Tiles of 128 same-type edges:
//   D[128,64] = H[128,64] @ W_t^T  via mma.sync m16n8k16 bf16 (3-product
//   Dekker split: hi*hi + hi*lo + lo*hi; fp32 accum; err ~2^-18).
// W rows [o][i] are directly the col-major B operand under plain ldmatrix.
// 8 warps/CTA, warp owns 16 edge rows; epilogue fuses in_deg^{-1/2} and
// scatters with red.global.add.v2.f32.
__global__ __launch_bounds__(256, 2) void rconv_hmma(
    const float2* __restrict__ feat2, float* __restrict__ acc)
{
    extern __shared__ __align__(16) char dynsmem[];
    __shared__ int s_cnt[NTYPES];
    __shared__ int s_tp[NTYPES + 1];

    const int tid  = threadIdx.x;
    const int wid  = tid >> 5;
    const int lane = tid & 31;

    uint32_t dyn0  = smem_u32(dynsmem);
    uint32_t abase = (dyn0 + 1023u) & ~1023u;   // 1024B align for swizzle
    char* sm   = dynsmem + (abase - dyn0);
    char* A_hi = sm;                 // 16KB : 128 rows x 128B (bf16 x 64)
    char* A_lo = sm + 16384;         // 16KB
    char* B_hi = sm + 32768;         // 8KB  : 64 rows x 128B
    char* B_lo = sm + 40960;         // 8KB
    const uint32_t A_hi_a = abase,         A_lo_a = abase + 16384;
    const uint32_t B_hi_a = abase + 32768, B_lo_a = abase + 40960;

    if (tid == 0) {
        int a = 0;
        for (int t = 0; t < NTYPES; t++) {
            int c = g_cursor[t];
            s_cnt[t] = c;
            s_tp[t] = a;
            a += (c + TILE_M - 1) / TILE_M;
        }
        s_tp[NTYPES] = a;
    }
    __syncthreads();
    const int n_tiles = s_tp[NTYPES];

    const int mbase = wid * 16;
    const int r8    = lane & 7;
    const int goff  = (lane >> 4) * 8;          // ldsm groups 2,3 -> rows +8
    const int khalf = ((lane >> 3) & 1) * 16;   // ldsm groups 1,3 -> k +8

    for (int tile = blockIdx.x; tile < n_tiles; tile += gridDim.x) {
        int t = 0;
        while (tile >= s_tp[t + 1]) t++;
        const int local = tile - s_tp[t];
        const int ebase = t * SEG_CAP + local * TILE_M;
        const int cnt   = s_cnt[t] - local * TILE_M;

        __syncthreads();   // previous tile fully consumed

        // ---- stage B: this type's W hi/lo, 64 rows x 128B, swizzled ----
        {
            const uint32_t* wh = (const uint32_t*)g_whi + (t << 11);
            const uint32_t* wl = (const uint32_t*)g_wlo + (t << 11);
            for (int idx = tid; idx < 2048; idx += 256) {
                int o = idx >> 5, c = idx & 31;
                uint32_t sw = SWZ((uint32_t)(o * 128 + c * 4));
                *(uint32_t*)(B_hi + sw) = wh[idx];
                *(uint32_t*)(B_lo + sw) = wl[idx];
            }
        }
        // ---- stage A: gather + outdeg scale + bf16 split, swizzled ----
        #pragma unroll 4
        for (int i = 0; i < 16; i++) {
            int m = mbase + i;
            bool val = m < cnt;
            int e = ebase + (val ? m : 0);
            int s = __ldg(&g_esrc[e]);
            float sc = val ? rsqrtf(fmaxf(__ldg(&g_deg_out[s]), 1.0f)) : 0.0f;
            float2 v = feat2[s * 32 + lane];
            float x0 = v.x * sc, x1 = v.y * sc;
            __nv_bfloat162 hi2 = __floats2bfloat162_rn(x0, x1);
            float2 hf = __bfloat1622float2(hi2);
            __nv_bfloat162 lo2 = __floats2bfloat162_rn(x0 - hf.x, x1 - hf.y);
            uint32_t sw = SWZ((uint32_t)(m * 128 + lane * 4));
            *(uint32_t*)(A_hi + sw) = *(uint32_t*)&hi2;
            *(uint32_t*)(A_lo + sw) = *(uint32_t*)&lo2;
        }
        __syncthreads();

        // ---- compute: 4 k-steps x 8 n-tiles x 3 products ----
        float c_[8][4];
        #pragma unroll
        for (int n = 0; n < 8; n++)
            #pragma unroll
            for (int j = 0; j < 4; j++) c_[n][j] = 0.f;

        #pragma unroll
        for (int ks = 0; ks < 4; ks++) {
            uint32_t ah[4], al[4];
            {
                uint32_t arow = mbase + (lane & 15);
                uint32_t ab = SWZ((uint32_t)(arow * 128 + ks * 32 + (lane >> 4) * 16));
                ldsm_x4(ah[0], ah[1], ah[2], ah[3], A_hi_a + ab);
                ldsm_x4(al[0], al[1], al[2], al[3], A_lo_a + ab);
            }
            uint32_t bh[8][2], bl[8][2];
            #pragma unroll
            for (int q = 0; q < 4; q++) {
                uint32_t o = 16 * q + goff + r8;
                uint32_t bb = SWZ((uint32_t)(o * 128 + ks * 32 + khalf));
                ldsm_x4(bh[2 * q][0], bh[2 * q][1], bh[2 * q + 1][0], bh[2 * q + 1][1],
                        B_hi_a + bb);
                ldsm_x4(bl[2 * q][0], bl[2 * q][1], bl[2 * q + 1][0], bl[2 * q + 1][1],
                        B_lo_a + bb);
            }
            #pragma unroll
            for (int n = 0; n < 8; n++) {
                mma_bf16(c_[n], ah, bh[n]);
                mma_bf16(c_[n], ah, bl[n]);
                mma_bf16(c_[n], al, bh[n]);
            }
        }

        // ---- epilogue: lane owns rows (mbase+lane/4, +8), cols 2*(lane&3)
        int r1 = mbase + (lane >> 2), r2 = r1 + 8;
        bool v1 = r1 < cnt, v2 = r2 < cnt;
        int dd1 = 0, dd2 = 0;
        float s1 = 0.f, s2 = 0.f;
        if (v1) { dd1 = __ldg(&g_edst[ebase + r1]); s1 = rsqrtf(fmaxf(__ldg(&g_deg_in[dd1]), 1.0f)); }
        if (v2) { dd2 = __ldg(&g_edst[ebase + r2]); s2 = rsqrtf(fmaxf(__ldg(&g_deg_in[dd2]), 1.0f)); }
        const int col = (lane & 3) * 2;
        #pragma unroll
        for (int n = 0; n < 8; n++) {
            if (v1) red2(acc + dd1 * F + n * 8 + col, c_[n][0] * s1, c_[n][1] * s1);
            if (v2) red2(acc + dd2 * F + n * 8 + col, c_[n][2] * s2, c_[n][3] * s2);
        }
    }
}

extern "C" void kernel_launch(void* const* d_in, const int* in_sizes, int n_in,
                              void* d_out, int out_size) {
    const float* feat = (const float*)d_in[0];
    const int*   src  = (const int*)  d_in[1];
    const int*   dst  = (const int*)  d_in[2];
    const int*   ordr = (const int*)  d_in[3];
    const float* emb  = (const float*)d_in[4];
    const float* bias = (const float*)d_in[5];
    float* out = (float*)d_out;

    static bool attr_set = false;
    if (!attr_set) {
        cudaFuncSetAttribute(rconv_hmma,
                             cudaFuncAttributeMaxDynamicSharedMemorySize,
                             SMEM_BYTES);
        attr_set = true;
    }

    rconv_prep<<<160, 256>>>(emb);
    rconv_init_scatter<<<(N_NODES * (F / 4) + 255) / 256, 256>>>(
        (float4*)out, (const float4*)bias, src, dst, ordr);
    rconv_hmma<<<592, 256, SMEM_BYTES>>>((const float2*)feat, out);
}